// round 15
// baseline (speedup 1.0000x reference)
#include <cuda_runtime.h>
#include <cuda_bf16.h>
#include <math.h>
#include <stdint.h>

#define B_  2
#define S_  2048
#define DM_ 512
#define H_  8
#define DK_ 64

// -------- device scratch (no allocations allowed) --------
__device__ float    g_sbval[H_*4096];        // bias value per (head, rel+2047)
__device__ uint32_t g_xh [4096*256], g_xl [4096*256];    // X rows x k-words
__device__ uint32_t g_wph[4*512*256], g_wpl[4*512*256];  // {Wq,Wk,Wv,Wo}: [n][k-word]
__device__ uint32_t g_qph[16*2048*32], g_qpl[16*2048*32]; // [bh][s][dk-word]
__device__ uint32_t g_kph[16*2048*32], g_kpl[16*2048*32];
__device__ uint32_t g_vth[16*64*1024], g_vtl[16*64*1024]; // V transposed: [bh][dk][key-word]
__device__ uint32_t g_aoh[4096*256],  g_aol[4096*256];    // attn out packed: [row][word]

// ---------------------------------------------------------
// helpers
// ---------------------------------------------------------
__device__ __forceinline__ uint32_t pack_bf2(float x0, float x1) {
    __nv_bfloat162 t = __floats2bfloat162_rn(x0, x1);   // .x = x0 (low half)
    return *(uint32_t*)&t;
}
__device__ __forceinline__ void split2(float x0, float x1, uint32_t& hi, uint32_t& lo) {
    float h0 = __bfloat162float(__float2bfloat16(x0));
    float h1 = __bfloat162float(__float2bfloat16(x1));
    hi = pack_bf2(h0, h1);
    lo = pack_bf2(x0 - h0, x1 - h1);
}
__device__ __forceinline__ void mma_bf16(float* d, const uint32_t* a, const uint32_t* b) {
    asm volatile(
        "mma.sync.aligned.m16n8k16.row.col.f32.bf16.bf16.f32 "
        "{%0,%1,%2,%3}, {%4,%5,%6,%7}, {%8,%9}, {%0,%1,%2,%3};"
        : "+f"(d[0]), "+f"(d[1]), "+f"(d[2]), "+f"(d[3])
        : "r"(a[0]), "r"(a[1]), "r"(a[2]), "r"(a[3]), "r"(b[0]), "r"(b[1]));
}
__device__ __forceinline__ void ldsm4(uint32_t* r, uint32_t addr) {
    asm volatile("ldmatrix.sync.aligned.m8n8.x4.shared.b16 {%0,%1,%2,%3}, [%4];"
        : "=r"(r[0]), "=r"(r[1]), "=r"(r[2]), "=r"(r[3]) : "r"(addr));
}
__device__ __forceinline__ uint32_t s2u(const void* p) {
    return (uint32_t)__cvta_generic_to_shared(p);
}
__device__ __forceinline__ void cpa16(uint32_t dst, const void* src) {
    asm volatile("cp.async.cg.shared.global [%0], [%1], 16;" :: "r"(dst), "l"(src));
}
__device__ __forceinline__ void cp_commit() {
    asm volatile("cp.async.commit_group;");
}

// ---------------------------------------------------------
// pack_all: fused setup (T5 bucket LUT -> g_sbval), pack_x, pack_w
// ---------------------------------------------------------
__global__ __launch_bounds__(256) void pack_all(const float* __restrict__ X,
                                                const float* __restrict__ Wq,
                                                const float* __restrict__ Wk,
                                                const float* __restrict__ Wv,
                                                const float* __restrict__ Wo,
                                                const float* __restrict__ emb) {
    int bx = blockIdx.x;
    int tid = threadIdx.x;
    if (bx < 4096) {
        int i = bx * 256 + tid;
        float2 v = *(const float2*)(X + 2 * (size_t)i);
        uint32_t h, l;
        split2(v.x, v.y, h, l);
        g_xh[i] = h; g_xl[i] = l;
    } else if (bx < 6144) {
        int e = (bx - 4096) * 256 + tid;
        int m  = e >> 17;
        int rem = e & 131071;
        int n  = rem >> 8;
        int kw = rem & 255;
        const float* W = (m == 0) ? Wq : (m == 1) ? Wk : (m == 2) ? Wv : Wo;
        float a = W[(size_t)(2 * kw) * 512 + n];
        float b = W[(size_t)(2 * kw + 1) * 512 + n];
        uint32_t h, l;
        split2(a, b, h, l);
        size_t idx = (size_t)m * 512 * 256 + (size_t)n * 256 + kw;
        g_wph[idx] = h; g_wpl[idx] = l;
    } else {
        int i = (bx - 6144) * 256 + tid;
        int d = i - (S_ - 1);
        int bucket = (d > 0) ? 16 : 0;
        int rel = d < 0 ? -d : d;
        int v;
        if (rel < 8) {
            v = rel;
        } else {
            float t = logf((float)rel / 8.0f);
            t = t / logf(16.0f);
            v = 8 + (int)(t * 8.0f);
            if (v > 15) v = 15;
        }
        int lutv = bucket + v;
        #pragma unroll
        for (int h = 0; h < H_; h++)
            g_sbval[h * 4096 + i] = emb[lutv * H_ + h];
    }
}

// =========================================================
// bf16-split mma GEMM core v2: BM=64, BN=128, BK=64,
// 128 thr / 4 warps, 2-stage cp.async, acc[16][4]/thread
// =========================================================
struct GemmSmem {
    uint32_t Ah[2][64][36],  Al[2][64][36];    // [stage][row][k-word]
    uint32_t Bh[2][128][36], Bl[2][128][36];   // [stage][n][k-word]
};

__device__ __forceinline__ void gemm_core(const uint32_t* __restrict__ Agh,
                                          const uint32_t* __restrict__ Agl,
                                          const uint32_t* __restrict__ Bgh,
                                          const uint32_t* __restrict__ Bgl,
                                          int bm, int bn,
                                          GemmSmem& sm, float acc[16][4]) {
    int tid  = threadIdx.x;
    int w    = tid >> 5;
    int lane = tid & 31;

    uint32_t a_off = (uint32_t)(((16*w + ((lane>>3)&1)*8 + (lane&7)) * 36 + (lane>>4)*4) * 4);
    uint32_t b_off = (uint32_t)((((lane>>4)*8 + (lane&7)) * 36 + ((lane>>3)&1)*4) * 4);
    uint32_t ah_b[2] = { s2u(&sm.Ah[0][0][0]), s2u(&sm.Ah[1][0][0]) };
    uint32_t al_b[2] = { s2u(&sm.Al[0][0][0]), s2u(&sm.Al[1][0][0]) };
    uint32_t bh_b[2] = { s2u(&sm.Bh[0][0][0]), s2u(&sm.Bh[1][0][0]) };
    uint32_t bl_b[2] = { s2u(&sm.Bl[0][0][0]), s2u(&sm.Bl[1][0][0]) };

    int ar = tid >> 1, ahalf = tid & 1;               // A: 64 rows, 2 thr/row
    uint32_t prowA = (uint32_t)((ar*36 + ahalf*16) * 4);

    auto issue = [&](int kb, int stg) {
        int kw0 = kb * 32;
        // A rows (hi+lo)
        {
            const char* pa_h = (const char*)(Agh + (size_t)(bm + ar) * 256 + kw0 + ahalf*16);
            const char* pa_l = (const char*)(Agl + (size_t)(bm + ar) * 256 + kw0 + ahalf*16);
            #pragma unroll
            for (int i = 0; i < 4; i++) {
                cpa16(ah_b[stg] + prowA + 16*i, pa_h + 16*i);
                cpa16(al_b[stg] + prowA + 16*i, pa_l + 16*i);
            }
        }
        // B rows: one full 128B row (hi and lo) per thread
        {
            const char* pb_h = (const char*)(Bgh + (size_t)(bn + tid) * 256 + kw0);
            const char* pb_l = (const char*)(Bgl + (size_t)(bn + tid) * 256 + kw0);
            uint32_t prowB = (uint32_t)(tid * 144);
            #pragma unroll
            for (int i = 0; i < 8; i++) {
                cpa16(bh_b[stg] + prowB + 16*i, pb_h + 16*i);
                cpa16(bl_b[stg] + prowB + 16*i, pb_l + 16*i);
            }
        }
        cp_commit();
    };

    issue(0, 0);
    for (int kb = 0; kb < 8; kb++) {
        int st = kb & 1;
        if (kb + 1 < 8) {
            issue(kb + 1, st ^ 1);
            asm volatile("cp.async.wait_group 1;");
        } else {
            asm volatile("cp.async.wait_group 0;");
        }
        __syncthreads();

        #pragma unroll
        for (int kk = 0; kk < 4; kk++) {
            uint32_t ah[4], al[4];
            ldsm4(ah, ah_b[st] + a_off + kk*32);
            ldsm4(al, al_b[st] + a_off + kk*32);
            #pragma unroll
            for (int jp = 0; jp < 8; jp++) {
                uint32_t bh4[4], bl4[4];
                ldsm4(bh4, bh_b[st] + b_off + jp*2304 + kk*32);
                ldsm4(bl4, bl_b[st] + b_off + jp*2304 + kk*32);
                mma_bf16(acc[2*jp],   ah, &bh4[0]);
                mma_bf16(acc[2*jp],   ah, &bl4[0]);
                mma_bf16(acc[2*jp],   al, &bh4[0]);
                mma_bf16(acc[2*jp+1], ah, &bh4[2]);
                mma_bf16(acc[2*jp+1], ah, &bl4[2]);
                mma_bf16(acc[2*jp+1], al, &bh4[2]);
            }
        }
        __syncthreads();
    }
}

// =========================================================
// qkv_fused: blocks [0,768) GEMM (g = bx>>6: mat = g>>2, ntile = g&3;
//   bm = (bx&63)*64, bn = ntile*128 spans TWO heads);
// blocks [768, 4864): position_bias rows
// =========================================================
__global__ __launch_bounds__(128) void qkv_fused(float* __restrict__ bias_out) {
    extern __shared__ char smem_raw[];
    int bx = blockIdx.x;
    int tid = threadIdx.x;

    if (bx >= 768) {
        int bb = bx - 768;               // 0..4095
        int h  = bb >> 9;
        int q0 = (bb & 511) * 4;
        #pragma unroll
        for (int rq = 0; rq < 4; rq++) {
            int q = q0 + rq;
            const float* src = g_sbval + h * 4096 + ((S_ - 1) - q);
            float* row = bias_out + ((size_t)h * S_ + q) * S_;
            #pragma unroll
            for (int k4 = tid * 4; k4 < S_; k4 += 128 * 4) {
                float4 o = make_float4(src[k4], src[k4+1], src[k4+2], src[k4+3]);
                *(float4*)&row[k4] = o;
            }
        }
        return;
    }

    GemmSmem& sm = *reinterpret_cast<GemmSmem*>(smem_raw);
    int g   = bx >> 6;        // 0..11
    int bm  = (bx & 63) * 64;
    int mat = g >> 2;
    int bn  = (g & 3) * 128;

    float acc[16][4];
    #pragma unroll
    for (int j = 0; j < 16; j++) { acc[j][0]=0.f; acc[j][1]=0.f; acc[j][2]=0.f; acc[j][3]=0.f; }

    gemm_core(g_xh, g_xl, g_wph + (size_t)mat*512*256, g_wpl + (size_t)mat*512*256,
              bm, bn, sm, acc);

    int lane = tid & 31;
    int r0 = 16 * (tid >> 5) + (lane >> 2);
    int c  = lane & 3;
    int m0 = bm + r0;
    int bb = m0 >> 11;
    int ss0 = m0 & 2047;
    int ss1 = (m0 + 8) & 2047;

    if (mat < 2) {
        uint32_t* dh = (mat == 0) ? g_qph : g_kph;
        uint32_t* dl = (mat == 0) ? g_qpl : g_kpl;
        #pragma unroll
        for (int j = 0; j < 16; j++) {
            int nj = bn + 8*j + 2*c;
            int hh = nj >> 6;
            int word = (nj & 63) >> 1;
            uint32_t hw, lw;
            size_t idx = ((size_t)(bb * H_ + hh) * 2048 + ss0) * 32 + word;
            split2(acc[j][0], acc[j][1], hw, lw);
            dh[idx] = hw; dl[idx] = lw;
            idx = ((size_t)(bb * H_ + hh) * 2048 + ss1) * 32 + word;
            split2(acc[j][2], acc[j][3], hw, lw);
            dh[idx] = hw; dl[idx] = lw;
        }
    } else {
        bool writer = (((lane >> 2) & 1) == 0);
        #pragma unroll
        for (int j = 0; j < 16; j++) {
            int nj = bn + 8*j + 2*c;
            int hh = nj >> 6;
            int dk0 = nj & 63;
            size_t base = (size_t)(bb * H_ + hh) * 64;
            float p0 = __shfl_xor_sync(0xffffffffu, acc[j][0], 4);
            float p1 = __shfl_xor_sync(0xffffffffu, acc[j][1], 4);
            float p2 = __shfl_xor_sync(0xffffffffu, acc[j][2], 4);
            float p3 = __shfl_xor_sync(0xffffffffu, acc[j][3], 4);
            if (writer) {
                uint32_t hw, lw;
                size_t i00 = (base + dk0    ) * 1024 + (ss0 >> 1);
                size_t i10 = (base + dk0 + 1) * 1024 + (ss0 >> 1);
                size_t i01 = (base + dk0    ) * 1024 + (ss1 >> 1);
                size_t i11 = (base + dk0 + 1) * 1024 + (ss1 >> 1);
                split2(acc[j][0], p0, hw, lw);  g_vth[i00] = hw;  g_vtl[i00] = lw;
                split2(acc[j][1], p1, hw, lw);  g_vth[i10] = hw;  g_vtl[i10] = lw;
                split2(acc[j][2], p2, hw, lw);  g_vth[i01] = hw;  g_vtl[i01] = lw;
                split2(acc[j][3], p3, hw, lw);  g_vth[i11] = hw;  g_vtl[i11] = lw;
            }
        }
    }
}

// =========================================================
// wo_gemm: grid 256 (mt = bx>>2, nt = bx&3), fp32 out
// =========================================================
__global__ __launch_bounds__(128) void wo_gemm(float* __restrict__ out) {
    extern __shared__ char smem_raw[];
    GemmSmem& sm = *reinterpret_cast<GemmSmem*>(smem_raw);
    int bx = blockIdx.x;
    int bm = (bx >> 2) * 64;
    int bn = (bx & 3) * 128;

    float acc[16][4];
    #pragma unroll
    for (int j = 0; j < 16; j++) { acc[j][0]=0.f; acc[j][1]=0.f; acc[j][2]=0.f; acc[j][3]=0.f; }

    gemm_core(g_aoh, g_aol, g_wph + (size_t)3*512*256, g_wpl + (size_t)3*512*256,
              bm, bn, sm, acc);

    int lane = threadIdx.x & 31;
    int r0 = 16 * (threadIdx.x >> 5) + (lane >> 2);
    int c  = lane & 3;
    #pragma unroll
    for (int j = 0; j < 16; j++) {
        int nn = bn + 8*j + 2*c;
        *(float2*)&out[(size_t)(bm + r0    ) * DM_ + nn] = make_float2(acc[j][0], acc[j][1]);
        *(float2*)&out[(size_t)(bm + r0 + 8) * DM_ + nn] = make_float2(acc[j][2], acc[j][3]);
    }
}

// =========================================================
// Flash attention v6 (unchanged, at HMMA floor): 128 q-rows/CTA,
// 256 thr / 8 warps, K 2-stage cp.async, V single-stage deferred,
// Q+P in regs, no online max. grid (16,16), 2 CTAs/SM.
// =========================================================
#define NT_ 32

struct AttnSmem {
    uint32_t Kh[2][64][36], Kl[2][64][36];
    uint32_t Vh[64][36],    Vl[64][36];
    float sb[2][192];
};

__global__ __launch_bounds__(256, 2) void attn_kernel() {
    extern __shared__ char smem_raw[];
    AttnSmem& sm = *reinterpret_cast<AttnSmem*>(smem_raw);

    int tid  = threadIdx.x;
    int w    = tid >> 5;
    int lane = tid & 31;
    int c    = lane & 3;
    const int r0 = 16 * w + (lane >> 2);

    int bh = blockIdx.x;
    int h  = bh & 7;
    int b  = bh >> 3;
    int q0 = blockIdx.y * 128;

    const float* sbh = g_sbval + h * 4096;

    int wl = w & 3;
    uint32_t a_off = (uint32_t)(((16*wl + ((lane>>3)&1)*8 + (lane&7)) * 36 + (lane>>4)*4) * 4);
    uint32_t b_off = (uint32_t)((((lane>>4)*8 + (lane&7)) * 36 + ((lane>>3)&1)*4) * 4);
    uint32_t kh_b[2] = { s2u(&sm.Kh[0][0][0]), s2u(&sm.Kh[1][0][0]) };
    uint32_t kl_b[2] = { s2u(&sm.Kl[0][0][0]), s2u(&sm.Kl[1][0][0]) };
    uint32_t vh_b = s2u(&sm.Vh[0][0]);
    uint32_t vl_b = s2u(&sm.Vl[0][0]);

    int pq  = tid >> 2;
    int qr4 = tid & 3;
    uint32_t prow4 = (uint32_t)(pq * 144 + qr4 * 32);

    // ---- prologue ----
    {
        const char* srcK_h = (const char*)(g_kph + ((size_t)bh*2048 + pq)*32 + qr4*8);
        const char* srcK_l = (const char*)(g_kpl + ((size_t)bh*2048 + pq)*32 + qr4*8);
        cpa16(kh_b[0] + prow4,      srcK_h);
        cpa16(kh_b[0] + prow4 + 16, srcK_h + 16);
        cpa16(kl_b[0] + prow4,      srcK_l);
        cpa16(kl_b[0] + prow4 + 16, srcK_l + 16);
        cp_commit();
    }
    {
        int pr = tid >> 1, phalf = tid & 1;
        const uint4* ph = (const uint4*)(g_qph + ((size_t)bh*2048 + q0 + pr)*32 + phalf*16);
        const uint4* pl = (const uint4*)(g_qpl + ((size_t)bh*2048 + q0 + pr)*32 + phalf*16);
        uint32_t dh = (pr < 64) ? kh_b[1] : vh_b;
        uint32_t dl = (pr < 64) ? kl_b[1] : vl_b;
        uint32_t off = (uint32_t)(((pr & 63) * 36 + phalf * 16) * 4);
        #pragma unroll
        for (int i = 0; i < 4; i++) {
            uint4 vh4 = ph[i], vl4 = pl[i];
            *(uint4*)((char*)smem_raw + (dh - s2u(smem_raw)) + off + 16*i) = vh4;
            *(uint4*)((char*)smem_raw + (dl - s2u(smem_raw)) + off + 16*i) = vl4;
        }
    }
    __syncthreads();
    uint32_t Qfh[4][4], Qfl[4][4];
    {
        uint32_t qsrc_h = (w < 4) ? kh_b[1] : vh_b;
        uint32_t qsrc_l = (w < 4) ? kl_b[1] : vl_b;
        #pragma unroll
        for (int kk = 0; kk < 4; kk++) {
            ldsm4(Qfh[kk], qsrc_h + a_off + kk*32);
            ldsm4(Qfl[kk], qsrc_l + a_off + kk*32);
        }
    }
    if (tid < 192) sm.sb[0][tid] = sbh[(0 - q0) + (S_ - 1) - 127 + tid];
    __syncthreads();

    float l0a = 0.f, l1a = 0.f;
    float O[8][4];
    #pragma unroll
    for (int j = 0; j < 8; j++) { O[j][0]=0.f; O[j][1]=0.f; O[j][2]=0.f; O[j][3]=0.f; }

    for (int t = 0; t < NT_; t++) {
        int st = t & 1;
        {
            int kw = t * 32;
            const char* srcV_h = (const char*)(g_vth + ((size_t)bh*64 + pq)*1024 + kw + qr4*8);
            const char* srcV_l = (const char*)(g_vtl + ((size_t)bh*64 + pq)*1024 + kw + qr4*8);
            cpa16(vh_b + prow4,      srcV_h);
            cpa16(vh_b + prow4 + 16, srcV_h + 16);
            cpa16(vl_b + prow4,      srcV_l);
            cpa16(vl_b + prow4 + 16, srcV_l + 16);
            cp_commit();
        }
        if (t + 1 < NT_) {
            int k1 = (t + 1) * 64;
            int ns = st ^ 1;
            const char* srcK_h = (const char*)(g_kph + ((size_t)bh*2048 + k1 + pq)*32 + qr4*8);
            const char* srcK_l = (const char*)(g_kpl + ((size_t)bh*2048 + k1 + pq)*32 + qr4*8);
            cpa16(kh_b[ns] + prow4,      srcK_h);
            cpa16(kh_b[ns] + prow4 + 16, srcK_h + 16);
            cpa16(kl_b[ns] + prow4,      srcK_l);
            cpa16(kl_b[ns] + prow4 + 16, srcK_l + 16);
            cp_commit();
            if (tid < 192) sm.sb[ns][tid] = sbh[(k1 - q0) + (S_ - 1) - 127 + tid];
            asm volatile("cp.async.wait_group 2;");
        } else {
            asm volatile("cp.async.wait_group 1;");
        }
        __syncthreads();

        float s[8][4];
        #pragma unroll
        for (int j = 0; j < 8; j++) {
            int cc = 8*j + 2*c;
            s[j][0] = sm.sb[st][127 + cc     - r0];
            s[j][1] = sm.sb[st][127 + cc + 1 - r0];
            s[j][2] = sm.sb[st][127 + cc     - r0 - 8];
            s[j][3] = sm.sb[st][127 + cc + 1 - r0 - 8];
        }

        #pragma unroll
        for (int kk = 0; kk < 4; kk++) {
            #pragma unroll
            for (int jp = 0; jp < 4; jp++) {
                uint32_t bh4[4], bl4[4];
                ldsm4(bh4, kh_b[st] + b_off + jp*2304 + kk*32);
                ldsm4(bl4, kl_b[st] + b_off + jp*2304 + kk*32);
                mma_bf16(s[2*jp],   Qfh[kk], &bh4[0]);
                mma_bf16(s[2*jp],   Qfh[kk], &bl4[0]);
                mma_bf16(s[2*jp],   Qfl[kk], &bh4[0]);
                mma_bf16(s[2*jp+1], Qfh[kk], &bh4[2]);
                mma_bf16(s[2*jp+1], Qfh[kk], &bl4[2]);
                mma_bf16(s[2*jp+1], Qfl[kk], &bh4[2]);
            }
        }

        #pragma unroll
        for (int j = 0; j < 8; j++) {
            s[j][0] = __expf(s[j][0]);
            s[j][1] = __expf(s[j][1]);
            s[j][2] = __expf(s[j][2]);
            s[j][3] = __expf(s[j][3]);
            l0a += s[j][0] + s[j][1];
            l1a += s[j][2] + s[j][3];
        }

        if (t + 1 < NT_) { asm volatile("cp.async.wait_group 1;"); }
        else             { asm volatile("cp.async.wait_group 0;"); }
        __syncthreads();

        #pragma unroll
        for (int kk = 0; kk < 4; kk++) {
            uint32_t ph[4], pl[4];
            split2(s[2*kk][0],   s[2*kk][1],   ph[0], pl[0]);
            split2(s[2*kk][2],   s[2*kk][3],   ph[1], pl[1]);
            split2(s[2*kk+1][0], s[2*kk+1][1], ph[2], pl[2]);
            split2(s[2*kk+1][2], s[2*kk+1][3], ph[3], pl[3]);
            #pragma unroll
            for (int jp = 0; jp < 4; jp++) {
                uint32_t bh4[4], bl4[4];
                ldsm4(bh4, vh_b + b_off + jp*2304 + kk*32);
                ldsm4(bl4, vl_b + b_off + jp*2304 + kk*32);
                mma_bf16(O[2*jp],   ph, &bh4[0]);
                mma_bf16(O[2*jp],   ph, &bl4[0]);
                mma_bf16(O[2*jp],   pl, &bh4[0]);
                mma_bf16(O[2*jp+1], ph, &bh4[2]);
                mma_bf16(O[2*jp+1], ph, &bl4[2]);
                mma_bf16(O[2*jp+1], pl, &bh4[2]);
            }
        }
        __syncthreads();
    }

    l0a += __shfl_xor_sync(0xffffffffu, l0a, 1);
    l0a += __shfl_xor_sync(0xffffffffu, l0a, 2);
    l1a += __shfl_xor_sync(0xffffffffu, l1a, 1);
    l1a += __shfl_xor_sync(0xffffffffu, l1a, 2);

    float inv0 = 1.0f / l0a, inv1 = 1.0f / l1a;
    size_t row0 = (size_t)b * S_ + q0 + r0;
    size_t row1 = row0 + 8;
    #pragma unroll
    for (int j = 0; j < 8; j++) {
        uint32_t hw, lw;
        size_t idx = row0 * 256 + h*32 + 4*j + c;
        split2(O[j][0]*inv0, O[j][1]*inv0, hw, lw);
        g_aoh[idx] = hw; g_aol[idx] = lw;
        idx = row1 * 256 + h*32 + 4*j + c;
        split2(O[j][2]*inv1, O[j][3]*inv1, hw, lw);
        g_aoh[idx] = hw; g_aol[idx] = lw;
    }
}

// ---------------------------------------------------------
extern "C" void kernel_launch(void* const* d_in, const int* in_sizes, int n_in,
                              void* d_out, int out_size) {
    const float* hs  = (const float*)d_in[0];
    const float* Wq  = (const float*)d_in[1];
    const float* Wk  = (const float*)d_in[2];
    const float* Wv  = (const float*)d_in[3];
    const float* Wo  = (const float*)d_in[4];
    const float* emb = (const float*)d_in[5];

    float* out      = (float*)d_out;
    float* attn_out = out;                               // [B,S,DM]
    float* bias_out = out + (size_t)B_ * S_ * DM_;       // [H,S,S]

    cudaFuncSetAttribute(attn_kernel,
                         cudaFuncAttributeMaxDynamicSharedMemorySize,
                         (int)sizeof(AttnSmem));
    cudaFuncSetAttribute(qkv_fused,
                         cudaFuncAttributeMaxDynamicSharedMemorySize,
                         (int)sizeof(GemmSmem));
    cudaFuncSetAttribute(wo_gemm,
                         cudaFuncAttributeMaxDynamicSharedMemorySize,
                         (int)sizeof(GemmSmem));

    pack_all<<<6160, 256>>>(hs, Wq, Wk, Wv, Wo, emb);
    qkv_fused<<<768 + 4096, 128, sizeof(GemmSmem)>>>(bias_out);
    attn_kernel<<<dim3(16, 16), 256, sizeof(AttnSmem)>>>();
    wo_gemm<<<256, 128, sizeof(GemmSmem)>>>(attn_out);
}

// round 17
// speedup vs baseline: 1.1431x; 1.1431x over previous
#include <cuda_runtime.h>
#include <cuda_bf16.h>
#include <math.h>
#include <stdint.h>

#define B_  2
#define S_  2048
#define DM_ 512
#define H_  8
#define DK_ 64

// -------- device scratch (no allocations allowed) --------
__device__ float    g_sbval[H_*4096];        // bias value per (head, rel+2047)
__device__ uint32_t g_xh [4096*256], g_xl [4096*256];    // X rows x k-words
__device__ uint32_t g_wph[4*512*256], g_wpl[4*512*256];  // {Wq,Wk,Wv,Wo}: [n][k-word]
__device__ uint32_t g_qph[16*2048*32], g_qpl[16*2048*32]; // [bh][s][dk-word]
__device__ uint32_t g_kph[16*2048*32], g_kpl[16*2048*32];
__device__ uint32_t g_vth[16*64*1024], g_vtl[16*64*1024]; // V transposed: [bh][dk][key-word]
__device__ uint32_t g_aoh[4096*256],  g_aol[4096*256];    // attn out packed: [row][word]

// ---------------------------------------------------------
// helpers
// ---------------------------------------------------------
__device__ __forceinline__ uint32_t pack_bf2(float x0, float x1) {
    __nv_bfloat162 t = __floats2bfloat162_rn(x0, x1);   // .x = x0 (low half)
    return *(uint32_t*)&t;
}
__device__ __forceinline__ void split2(float x0, float x1, uint32_t& hi, uint32_t& lo) {
    float h0 = __bfloat162float(__float2bfloat16(x0));
    float h1 = __bfloat162float(__float2bfloat16(x1));
    hi = pack_bf2(h0, h1);
    lo = pack_bf2(x0 - h0, x1 - h1);
}
__device__ __forceinline__ void mma_bf16(float* d, const uint32_t* a, const uint32_t* b) {
    asm volatile(
        "mma.sync.aligned.m16n8k16.row.col.f32.bf16.bf16.f32 "
        "{%0,%1,%2,%3}, {%4,%5,%6,%7}, {%8,%9}, {%0,%1,%2,%3};"
        : "+f"(d[0]), "+f"(d[1]), "+f"(d[2]), "+f"(d[3])
        : "r"(a[0]), "r"(a[1]), "r"(a[2]), "r"(a[3]), "r"(b[0]), "r"(b[1]));
}
__device__ __forceinline__ void ldsm4(uint32_t* r, uint32_t addr) {
    asm volatile("ldmatrix.sync.aligned.m8n8.x4.shared.b16 {%0,%1,%2,%3}, [%4];"
        : "=r"(r[0]), "=r"(r[1]), "=r"(r[2]), "=r"(r[3]) : "r"(addr));
}
__device__ __forceinline__ uint32_t s2u(const void* p) {
    return (uint32_t)__cvta_generic_to_shared(p);
}
__device__ __forceinline__ void cpa16(uint32_t dst, const void* src) {
    asm volatile("cp.async.cg.shared.global [%0], [%1], 16;" :: "r"(dst), "l"(src));
}
__device__ __forceinline__ void cp_commit() {
    asm volatile("cp.async.commit_group;");
}

// ---------------------------------------------------------
// pack_all: fused setup (T5 bucket LUT -> g_sbval), pack_x, pack_w
// ---------------------------------------------------------
__global__ __launch_bounds__(256) void pack_all(const float* __restrict__ X,
                                                const float* __restrict__ Wq,
                                                const float* __restrict__ Wk,
                                                const float* __restrict__ Wv,
                                                const float* __restrict__ Wo,
                                                const float* __restrict__ emb) {
    int bx = blockIdx.x;
    int tid = threadIdx.x;
    if (bx < 4096) {
        int i = bx * 256 + tid;
        float2 v = *(const float2*)(X + 2 * (size_t)i);
        uint32_t h, l;
        split2(v.x, v.y, h, l);
        g_xh[i] = h; g_xl[i] = l;
    } else if (bx < 6144) {
        int e = (bx - 4096) * 256 + tid;
        int m  = e >> 17;
        int rem = e & 131071;
        int n  = rem >> 8;
        int kw = rem & 255;
        const float* W = (m == 0) ? Wq : (m == 1) ? Wk : (m == 2) ? Wv : Wo;
        float a = W[(size_t)(2 * kw) * 512 + n];
        float b = W[(size_t)(2 * kw + 1) * 512 + n];
        uint32_t h, l;
        split2(a, b, h, l);
        size_t idx = (size_t)m * 512 * 256 + (size_t)n * 256 + kw;
        g_wph[idx] = h; g_wpl[idx] = l;
    } else {
        int i = (bx - 6144) * 256 + tid;
        int d = i - (S_ - 1);
        int bucket = (d > 0) ? 16 : 0;
        int rel = d < 0 ? -d : d;
        int v;
        if (rel < 8) {
            v = rel;
        } else {
            float t = logf((float)rel / 8.0f);
            t = t / logf(16.0f);
            v = 8 + (int)(t * 8.0f);
            if (v > 15) v = 15;
        }
        int lutv = bucket + v;
        #pragma unroll
        for (int h = 0; h < H_; h++)
            g_sbval[h * 4096 + i] = emb[lutv * H_ + h];
    }
}

// =========================================================
// bf16-split mma GEMM core v3: BM=64, BN=64, BK=32,
// 16 chunks, 2-stage cp.async, 40KB smem -> 5 CTAs/SM
// =========================================================
struct GemmSmem {
    uint32_t Ah[2][64][20], Al[2][64][20];   // [stage][row][k-word] (16 used, stride 20)
    uint32_t Bh[2][64][20], Bl[2][64][20];   // [stage][n][k-word]
};

__device__ __forceinline__ void gemm_core(const uint32_t* __restrict__ Agh,
                                          const uint32_t* __restrict__ Agl,
                                          const uint32_t* __restrict__ Bgh,
                                          const uint32_t* __restrict__ Bgl,
                                          int bm, int bn,
                                          GemmSmem& sm, float acc[8][4]) {
    int tid  = threadIdx.x;
    int w    = tid >> 5;
    int lane = tid & 31;

    uint32_t a_off = (uint32_t)(((16*w + ((lane>>3)&1)*8 + (lane&7)) * 20 + (lane>>4)*4) * 4);
    uint32_t b_off = (uint32_t)((((lane>>4)*8 + (lane&7)) * 20 + ((lane>>3)&1)*4) * 4);
    uint32_t ah_b[2] = { s2u(&sm.Ah[0][0][0]), s2u(&sm.Ah[1][0][0]) };
    uint32_t al_b[2] = { s2u(&sm.Al[0][0][0]), s2u(&sm.Al[1][0][0]) };
    uint32_t bh_b[2] = { s2u(&sm.Bh[0][0][0]), s2u(&sm.Bh[1][0][0]) };
    uint32_t bl_b[2] = { s2u(&sm.Bl[0][0][0]), s2u(&sm.Bl[1][0][0]) };

    int r = tid >> 1, half = tid & 1;          // row, 8-word half (32B)
    uint32_t prow = (uint32_t)((r*20 + half*8) * 4);

    auto issue = [&](int kb, int stg) {
        int kw0 = kb * 16 + half * 8;
        const char* pa_h = (const char*)(Agh + (size_t)(bm + r) * 256 + kw0);
        const char* pa_l = (const char*)(Agl + (size_t)(bm + r) * 256 + kw0);
        const char* pb_h = (const char*)(Bgh + (size_t)(bn + r) * 256 + kw0);
        const char* pb_l = (const char*)(Bgl + (size_t)(bn + r) * 256 + kw0);
        #pragma unroll
        for (int i = 0; i < 2; i++) {
            cpa16(ah_b[stg] + prow + 16*i, pa_h + 16*i);
            cpa16(al_b[stg] + prow + 16*i, pa_l + 16*i);
            cpa16(bh_b[stg] + prow + 16*i, pb_h + 16*i);
            cpa16(bl_b[stg] + prow + 16*i, pb_l + 16*i);
        }
        cp_commit();
    };

    issue(0, 0);
    for (int kb = 0; kb < 16; kb++) {
        int st = kb & 1;
        if (kb + 1 < 16) {
            issue(kb + 1, st ^ 1);
            asm volatile("cp.async.wait_group 1;");
        } else {
            asm volatile("cp.async.wait_group 0;");
        }
        __syncthreads();

        #pragma unroll
        for (int kk = 0; kk < 2; kk++) {
            uint32_t ah[4], al[4];
            ldsm4(ah, ah_b[st] + a_off + kk*32);
            ldsm4(al, al_b[st] + a_off + kk*32);
            #pragma unroll
            for (int jp = 0; jp < 4; jp++) {
                uint32_t bh4[4], bl4[4];
                ldsm4(bh4, bh_b[st] + b_off + jp*1280 + kk*32);   // 16 rows * 20 words * 4B
                ldsm4(bl4, bl_b[st] + b_off + jp*1280 + kk*32);
                mma_bf16(acc[2*jp],   ah, &bh4[0]);
                mma_bf16(acc[2*jp],   ah, &bl4[0]);
                mma_bf16(acc[2*jp],   al, &bh4[0]);
                mma_bf16(acc[2*jp+1], ah, &bh4[2]);
                mma_bf16(acc[2*jp+1], ah, &bl4[2]);
                mma_bf16(acc[2*jp+1], al, &bh4[2]);
            }
        }
        __syncthreads();
    }
}

// =========================================================
// qkv_fused: blocks [0,1536) GEMM; [1536,5632) bias rows
// =========================================================
__global__ __launch_bounds__(128) void qkv_fused(float* __restrict__ bias_out) {
    extern __shared__ char smem_raw[];
    int bx = blockIdx.x;
    int tid = threadIdx.x;

    if (bx >= 1536) {
        int bb = bx - 1536;
        int h  = bb >> 9;
        int q0 = (bb & 511) * 4;
        #pragma unroll
        for (int rq = 0; rq < 4; rq++) {
            int q = q0 + rq;
            const float* src = g_sbval + h * 4096 + ((S_ - 1) - q);
            float* row = bias_out + ((size_t)h * S_ + q) * S_;
            #pragma unroll
            for (int k4 = tid * 4; k4 < S_; k4 += 128 * 4) {
                float4 o = make_float4(src[k4], src[k4+1], src[k4+2], src[k4+3]);
                *(float4*)&row[k4] = o;
            }
        }
        return;
    }

    GemmSmem& sm = *reinterpret_cast<GemmSmem*>(smem_raw);
    int nt = bx >> 6;
    int bm = (bx & 63) * 64;
    int mat = nt >> 3;
    int hh  = nt & 7;

    float acc[8][4];
    #pragma unroll
    for (int j = 0; j < 8; j++) { acc[j][0]=0.f; acc[j][1]=0.f; acc[j][2]=0.f; acc[j][3]=0.f; }

    gemm_core(g_xh, g_xl, g_wph + (size_t)mat*512*256, g_wpl + (size_t)mat*512*256,
              bm, hh * 64, sm, acc);

    int lane = tid & 31;
    int r0 = 16 * (tid >> 5) + (lane >> 2);
    int c  = lane & 3;

    if (mat < 2) {
        uint32_t* dh = (mat == 0) ? g_qph : g_kph;
        uint32_t* dl = (mat == 0) ? g_qpl : g_kpl;
        #pragma unroll
        for (int j = 0; j < 8; j++) {
            uint32_t hw, lw;
            int m0 = bm + r0;
            int bb = m0 >> 11, ss = m0 & 2047;
            size_t idx = ((size_t)(bb * H_ + hh) * 2048 + ss) * 32 + 4*j + c;
            split2(acc[j][0], acc[j][1], hw, lw);
            dh[idx] = hw; dl[idx] = lw;
            int m1 = m0 + 8;
            bb = m1 >> 11; ss = m1 & 2047;
            idx = ((size_t)(bb * H_ + hh) * 2048 + ss) * 32 + 4*j + c;
            split2(acc[j][2], acc[j][3], hw, lw);
            dh[idx] = hw; dl[idx] = lw;
        }
    } else {
        int m0 = bm + r0;
        int bb = m0 >> 11;
        int ss0 = m0 & 2047;
        int ss1 = (m0 + 8) & 2047;
        size_t base = (size_t)(bb * H_ + hh) * 64;
        bool writer = (((lane >> 2) & 1) == 0);
        #pragma unroll
        for (int j = 0; j < 8; j++) {
            float p0 = __shfl_xor_sync(0xffffffffu, acc[j][0], 4);
            float p1 = __shfl_xor_sync(0xffffffffu, acc[j][1], 4);
            float p2 = __shfl_xor_sync(0xffffffffu, acc[j][2], 4);
            float p3 = __shfl_xor_sync(0xffffffffu, acc[j][3], 4);
            if (writer) {
                int dk0 = 8*j + 2*c;
                uint32_t hw, lw;
                size_t i00 = (base + dk0    ) * 1024 + (ss0 >> 1);
                size_t i10 = (base + dk0 + 1) * 1024 + (ss0 >> 1);
                size_t i01 = (base + dk0    ) * 1024 + (ss1 >> 1);
                size_t i11 = (base + dk0 + 1) * 1024 + (ss1 >> 1);
                split2(acc[j][0], p0, hw, lw);  g_vth[i00] = hw;  g_vtl[i00] = lw;
                split2(acc[j][1], p1, hw, lw);  g_vth[i10] = hw;  g_vtl[i10] = lw;
                split2(acc[j][2], p2, hw, lw);  g_vth[i01] = hw;  g_vtl[i01] = lw;
                split2(acc[j][3], p3, hw, lw);  g_vth[i11] = hw;  g_vtl[i11] = lw;
            }
        }
    }
}

// WO: grid (64, 8)
__global__ __launch_bounds__(128) void wo_gemm(float* __restrict__ out) {
    extern __shared__ char smem_raw[];
    GemmSmem& sm = *reinterpret_cast<GemmSmem*>(smem_raw);
    int bm = blockIdx.x * 64;
    int bn = blockIdx.y * 64;

    float acc[8][4];
    #pragma unroll
    for (int j = 0; j < 8; j++) { acc[j][0]=0.f; acc[j][1]=0.f; acc[j][2]=0.f; acc[j][3]=0.f; }

    gemm_core(g_aoh, g_aol, g_wph + (size_t)3*512*256, g_wpl + (size_t)3*512*256,
              bm, bn, sm, acc);

    int lane = threadIdx.x & 31;
    int r0 = 16 * (threadIdx.x >> 5) + (lane >> 2);
    int c  = lane & 3;
    #pragma unroll
    for (int j = 0; j < 8; j++) {
        int nn = 8*j + 2*c;
        *(float2*)&out[(size_t)(bm + r0    ) * DM_ + bn + nn] = make_float2(acc[j][0], acc[j][1]);
        *(float2*)&out[(size_t)(bm + r0 + 8) * DM_ + bn + nn] = make_float2(acc[j][2], acc[j][3]);
    }
}

// =========================================================
// Flash attention v6 (unchanged, at HMMA floor): 128 q-rows/CTA,
// 256 thr / 8 warps, K 2-stage cp.async, V single-stage deferred,
// Q+P in regs, no online max. grid (16,16), 2 CTAs/SM.
// =========================================================
#define NT_ 32

struct AttnSmem {
    uint32_t Kh[2][64][36], Kl[2][64][36];
    uint32_t Vh[64][36],    Vl[64][36];
    float sb[2][192];
};

__global__ __launch_bounds__(256, 2) void attn_kernel() {
    extern __shared__ char smem_raw[];
    AttnSmem& sm = *reinterpret_cast<AttnSmem*>(smem_raw);

    int tid  = threadIdx.x;
    int w    = tid >> 5;
    int lane = tid & 31;
    int c    = lane & 3;
    const int r0 = 16 * w + (lane >> 2);

    int bh = blockIdx.x;
    int h  = bh & 7;
    int b  = bh >> 3;
    int q0 = blockIdx.y * 128;

    const float* sbh = g_sbval + h * 4096;

    int wl = w & 3;
    uint32_t a_off = (uint32_t)(((16*wl + ((lane>>3)&1)*8 + (lane&7)) * 36 + (lane>>4)*4) * 4);
    uint32_t b_off = (uint32_t)((((lane>>4)*8 + (lane&7)) * 36 + ((lane>>3)&1)*4) * 4);
    uint32_t kh_b[2] = { s2u(&sm.Kh[0][0][0]), s2u(&sm.Kh[1][0][0]) };
    uint32_t kl_b[2] = { s2u(&sm.Kl[0][0][0]), s2u(&sm.Kl[1][0][0]) };
    uint32_t vh_b = s2u(&sm.Vh[0][0]);
    uint32_t vl_b = s2u(&sm.Vl[0][0]);

    int pq  = tid >> 2;
    int qr4 = tid & 3;
    uint32_t prow4 = (uint32_t)(pq * 144 + qr4 * 32);

    // ---- prologue ----
    {
        const char* srcK_h = (const char*)(g_kph + ((size_t)bh*2048 + pq)*32 + qr4*8);
        const char* srcK_l = (const char*)(g_kpl + ((size_t)bh*2048 + pq)*32 + qr4*8);
        cpa16(kh_b[0] + prow4,      srcK_h);
        cpa16(kh_b[0] + prow4 + 16, srcK_h + 16);
        cpa16(kl_b[0] + prow4,      srcK_l);
        cpa16(kl_b[0] + prow4 + 16, srcK_l + 16);
        cp_commit();
    }
    {
        int pr = tid >> 1, phalf = tid & 1;
        const uint4* ph = (const uint4*)(g_qph + ((size_t)bh*2048 + q0 + pr)*32 + phalf*16);
        const uint4* pl = (const uint4*)(g_qpl + ((size_t)bh*2048 + q0 + pr)*32 + phalf*16);
        uint32_t dh = (pr < 64) ? kh_b[1] : vh_b;
        uint32_t dl = (pr < 64) ? kl_b[1] : vl_b;
        uint32_t off = (uint32_t)(((pr & 63) * 36 + phalf * 16) * 4);
        #pragma unroll
        for (int i = 0; i < 4; i++) {
            uint4 vh4 = ph[i], vl4 = pl[i];
            *(uint4*)((char*)smem_raw + (dh - s2u(smem_raw)) + off + 16*i) = vh4;
            *(uint4*)((char*)smem_raw + (dl - s2u(smem_raw)) + off + 16*i) = vl4;
        }
    }
    __syncthreads();
    uint32_t Qfh[4][4], Qfl[4][4];
    {
        uint32_t qsrc_h = (w < 4) ? kh_b[1] : vh_b;
        uint32_t qsrc_l = (w < 4) ? kl_b[1] : vl_b;
        #pragma unroll
        for (int kk = 0; kk < 4; kk++) {
            ldsm4(Qfh[kk], qsrc_h + a_off + kk*32);
            ldsm4(Qfl[kk], qsrc_l + a_off + kk*32);
        }
    }
    if (tid < 192) sm.sb[0][tid] = sbh[(0 - q0) + (S_ - 1) - 127 + tid];
    __syncthreads();

    float l0a = 0.f, l1a = 0.f;
    float O[8][4];
    #pragma unroll
    for (int j = 0; j < 8; j++) { O[j][0]=0.f; O[j][1]=0.f; O[j][2]=0.f; O[j][3]=0.f; }

    for (int t = 0; t < NT_; t++) {
        int st = t & 1;
        {
            int kw = t * 32;
            const char* srcV_h = (const char*)(g_vth + ((size_t)bh*64 + pq)*1024 + kw + qr4*8);
            const char* srcV_l = (const char*)(g_vtl + ((size_t)bh*64 + pq)*1024 + kw + qr4*8);
            cpa16(vh_b + prow4,      srcV_h);
            cpa16(vh_b + prow4 + 16, srcV_h + 16);
            cpa16(vl_b + prow4,      srcV_l);
            cpa16(vl_b + prow4 + 16, srcV_l + 16);
            cp_commit();
        }
        if (t + 1 < NT_) {
            int k1 = (t + 1) * 64;
            int ns = st ^ 1;
            const char* srcK_h = (const char*)(g_kph + ((size_t)bh*2048 + k1 + pq)*32 + qr4*8);
            const char* srcK_l = (const char*)(g_kpl + ((size_t)bh*2048 + k1 + pq)*32 + qr4*8);
            cpa16(kh_b[ns] + prow4,      srcK_h);
            cpa16(kh_b[ns] + prow4 + 16, srcK_h + 16);
            cpa16(kl_b[ns] + prow4,      srcK_l);
            cpa16(kl_b[ns] + prow4 + 16, srcK_l + 16);
            cp_commit();
            if (tid < 192) sm.sb[ns][tid] = sbh[(k1 - q0) + (S_ - 1) - 127 + tid];
            asm volatile("cp.async.wait_group 2;");
        } else {
            asm volatile("cp.async.wait_group 1;");
        }
        __syncthreads();

        float s[8][4];
        #pragma unroll
        for (int j = 0; j < 8; j++) {
            int cc = 8*j + 2*c;
            s[j][0] = sm.sb[st][127 + cc     - r0];
            s[j][1] = sm.sb[st][127 + cc + 1 - r0];
            s[j][2] = sm.sb[st][127 + cc     - r0 - 8];
            s[j][3] = sm.sb[st][127 + cc + 1 - r0 - 8];
        }

        #pragma unroll
        for (int kk = 0; kk < 4; kk++) {
            #pragma unroll
            for (int jp = 0; jp < 4; jp++) {
                uint32_t bh4[4], bl4[4];
                ldsm4(bh4, kh_b[st] + b_off + jp*2304 + kk*32);
                ldsm4(bl4, kl_b[st] + b_off + jp*2304 + kk*32);
                mma_bf16(s[2*jp],   Qfh[kk], &bh4[0]);
                mma_bf16(s[2*jp],   Qfh[kk], &bl4[0]);
                mma_bf16(s[2*jp],   Qfl[kk], &bh4[0]);
                mma_bf16(s[2*jp+1], Qfh[kk], &bh4[2]);
                mma_bf16(s[2*jp+1], Qfh[kk], &bl4[2]);
                mma_bf16(s[2*jp+1], Qfl[kk], &bh4[2]);
            }
        }

        #pragma unroll
        for (int j = 0; j < 8; j++) {
            s[j][0] = __expf(s[j][0]);
            s[j][1] = __expf(s[j][1]);
            s[j][2] = __expf(s[j][2]);
            s[j][3] = __expf(s[j][3]);
            l0a += s[j][0] + s[j][1];
            l1a += s[j][2] + s[j][3];
        }

        if (t + 1 < NT_) { asm volatile("cp.async.wait_group 1;"); }
        else             { asm volatile("cp.async.wait_group 0;"); }
        __syncthreads();

        #pragma unroll
        for (int kk = 0; kk < 4; kk++) {
            uint32_t ph[4], pl[4];
            split2(s[2*kk][0],   s[2*kk][1],   ph[0], pl[0]);
            split2(s[2*kk][2],   s[2*kk][3],   ph[1], pl[1]);
            split2(s[2*kk+1][0], s[2*kk+1][1], ph[2], pl[2]);
            split2(s[2*kk+1][2], s[2*kk+1][3], ph[3], pl[3]);
            #pragma unroll
            for (int jp = 0; jp < 4; jp++) {
                uint32_t bh4[4], bl4[4];
                ldsm4(bh4, vh_b + b_off + jp*2304 + kk*32);
                ldsm4(bl4, vl_b + b_off + jp*2304 + kk*32);
                mma_bf16(O[2*jp],   ph, &bh4[0]);
                mma_bf16(O[2*jp],   ph, &bl4[0]);
                mma_bf16(O[2*jp],   pl, &bh4[0]);
                mma_bf16(O[2*jp+1], ph, &bh4[2]);
                mma_bf16(O[2*jp+1], ph, &bl4[2]);
                mma_bf16(O[2*jp+1], pl, &bh4[2]);
            }
        }
        __syncthreads();
    }

    l0a += __shfl_xor_sync(0xffffffffu, l0a, 1);
    l0a += __shfl_xor_sync(0xffffffffu, l0a, 2);
    l1a += __shfl_xor_sync(0xffffffffu, l1a, 1);
    l1a += __shfl_xor_sync(0xffffffffu, l1a, 2);

    float inv0 = 1.0f / l0a, inv1 = 1.0f / l1a;
    size_t row0 = (size_t)b * S_ + q0 + r0;
    size_t row1 = row0 + 8;
    #pragma unroll
    for (int j = 0; j < 8; j++) {
        uint32_t hw, lw;
        size_t idx = row0 * 256 + h*32 + 4*j + c;
        split2(O[j][0]*inv0, O[j][1]*inv0, hw, lw);
        g_aoh[idx] = hw; g_aol[idx] = lw;
        idx = row1 * 256 + h*32 + 4*j + c;
        split2(O[j][2]*inv1, O[j][3]*inv1, hw, lw);
        g_aoh[idx] = hw; g_aol[idx] = lw;
    }
}

// ---------------------------------------------------------
extern "C" void kernel_launch(void* const* d_in, const int* in_sizes, int n_in,
                              void* d_out, int out_size) {
    const float* hs  = (const float*)d_in[0];
    const float* Wq  = (const float*)d_in[1];
    const float* Wk  = (const float*)d_in[2];
    const float* Wv  = (const float*)d_in[3];
    const float* Wo  = (const float*)d_in[4];
    const float* emb = (const float*)d_in[5];

    float* out      = (float*)d_out;
    float* attn_out = out;                               // [B,S,DM]
    float* bias_out = out + (size_t)B_ * S_ * DM_;       // [H,S,S]

    cudaFuncSetAttribute(attn_kernel,
                         cudaFuncAttributeMaxDynamicSharedMemorySize,
                         (int)sizeof(AttnSmem));
    cudaFuncSetAttribute(qkv_fused,
                         cudaFuncAttributeMaxDynamicSharedMemorySize,
                         (int)sizeof(GemmSmem));
    cudaFuncSetAttribute(wo_gemm,
                         cudaFuncAttributeMaxDynamicSharedMemorySize,
                         (int)sizeof(GemmSmem));

    pack_all<<<6160, 256>>>(hs, Wq, Wk, Wv, Wo, emb);
    qkv_fused<<<5632, 128, sizeof(GemmSmem)>>>(bias_out);
    attn_kernel<<<dim3(16, 16), 256, sizeof(AttnSmem)>>>();
    wo_gemm<<<dim3(64, 8), 128, sizeof(GemmSmem)>>>(attn_out);
}